// round 12
// baseline (speedup 1.0000x reference)
#include <cuda_runtime.h>
#include <cuda_fp16.h>
#include <cstdint>

// ---------------------------------------------------------------------------
// Problem constants
// ---------------------------------------------------------------------------
#define BATCH     8
#define KPTS      4096
#define NPTS      (BATCH * KPTS)      // 32768
#define DM        192
#define DIN       800
#define PEW       32
#define PIX_PB    21760               // 16384+4096+1024+256
#define TPB64     340                 // 64-px tiles per batch
#define NPE_BLK   (NPTS / 64)         // 512
#define NGEMM_BLK (BATCH * TPB64)     // 2720

__device__ __constant__ int c_HW[4]    = {16384, 4096, 1024, 256};
__device__ __constant__ int c_Wd[4]    = {128, 64, 32, 16};
__device__ __constant__ int c_LOFF[4]  = {0, 16384, 20480, 21504};

// ---------------------------------------------------------------------------
// Static device scratch
// ---------------------------------------------------------------------------
__device__ __half g_P[(size_t)BATCH * PIX_PB * DM];   // projected maps [pix][d] fp16
__device__ __half g_peW[(size_t)NPTS * DM];           // PE @ Wseed_pe^T  (fp16)
__device__ __half g_Wbf[4][DM][DM];                   // [level][d][c] fp16
__device__ __half g_Wbfpe[2][DM][PEW];                // [z][d][j]
// per-point gather metadata: [pt][level] {int4 corner byte-offsets, 4x half2 weights}
__device__ uint4 g_meta[(size_t)NPTS * 8];            // 128B per point (4 MB)

// ---------------------------------------------------------------------------
// PTX helpers (generic sm_80+ — safe on compute_103 target)
// ---------------------------------------------------------------------------
__device__ __forceinline__ uint32_t smem_u32(const void* p) {
    uint32_t a;
    asm("{ .reg .u64 t; cvta.to.shared.u64 t, %1; cvt.u32.u64 %0, t; }" : "=r"(a) : "l"(p));
    return a;
}
__device__ __forceinline__ void ldmx4(uint32_t r[4], uint32_t addr) {
    asm volatile("ldmatrix.sync.aligned.m8n8.x4.shared.b16 {%0,%1,%2,%3}, [%4];"
                 : "=r"(r[0]), "=r"(r[1]), "=r"(r[2]), "=r"(r[3]) : "r"(addr));
}
__device__ __forceinline__ void mma_f16(float c[4], const uint32_t a[4],
                                        uint32_t b0, uint32_t b1) {
    asm volatile("mma.sync.aligned.m16n8k16.row.col.f32.f16.f16.f32 "
                 "{%0,%1,%2,%3}, {%4,%5,%6,%7}, {%8,%9}, {%0,%1,%2,%3};"
                 : "+f"(c[0]), "+f"(c[1]), "+f"(c[2]), "+f"(c[3])
                 : "r"(a[0]), "r"(a[1]), "r"(a[2]), "r"(a[3]), "r"(b0), "r"(b1));
}
#define CP_ASYNC16(dst, src) \
    asm volatile("cp.async.cg.shared.global [%0], [%1], 16;" \
                 :: "r"(dst), "l"(src) : "memory")
#define CP_COMMIT()  asm volatile("cp.async.commit_group;" ::: "memory")
#define CP_WAIT0()   asm volatile("cp.async.wait_group 0;" ::: "memory")

// ---------------------------------------------------------------------------
// Kernel 1: weight prep — fp16 weights (float4-vectorized)
// ---------------------------------------------------------------------------
#define PREP_N ((4 * DM * DM + 2 * DM * PEW) / 4)
__global__ void __launch_bounds__(256) k_prep(const float* __restrict__ Wseed_w,
                                              const float* __restrict__ Wpos_w) {
    int idx = blockIdx.x * 256 + threadIdx.x;
    if (idx < DM * DM) {
        int l = (idx * 4) / (DM * DM);
        int rem = (idx * 4) % (DM * DM);
        int d = rem / DM, c = rem % DM;
        float4 w = *(const float4*)(Wseed_w + (size_t)d * DIN + l * DM + c);
        __half* dst = &g_Wbf[l][d][c];
        dst[0] = __float2half_rn(w.x); dst[1] = __float2half_rn(w.y);
        dst[2] = __float2half_rn(w.z); dst[3] = __float2half_rn(w.w);
    } else if (idx < PREP_N) {
        int i2 = (idx - DM * DM) * 4;
        int z = i2 / (DM * PEW);
        int rem = i2 % (DM * PEW);
        int d = rem / PEW, j = rem % PEW;
        const float* src = z ? (Wpos_w + (size_t)d * PEW + j)
                             : (Wseed_w + (size_t)d * DIN + 768 + j);
        float4 w = *(const float4*)src;
        __half* dst = &g_Wbfpe[z][d][j];
        dst[0] = __float2half_rn(w.x); dst[1] = __float2half_rn(w.y);
        dst[2] = __float2half_rn(w.z); dst[3] = __float2half_rn(w.w);
    }
}

// ---------------------------------------------------------------------------
// Fused main kernel (128 threads/block, 3 CTAs/SM — proven R9/R11 structure):
//   blocks [0, NGEMM_BLK):          projection GEMM (64px x 192d per block)
//   blocks [NGEMM_BLK, +NPE_BLK):   PE + dual GEMM + center_grid + gather meta
// ---------------------------------------------------------------------------
#define SM_BSH 0                      // Bs [192][72] half = 27648
#define SM_ASH 27648                  // As [64][72] half  = 9216
#define SM_FS0 36864                  // Fs x2 buffers fp32 [64][68]
#define FS_SZ  17408
#define SMEM_MAIN (SM_FS0 + 2 * FS_SZ)   // 71680
// pegemm-part smem layout (within same allocation)
#define PG_AS0 0                      // As [64][40] half = 5120
#define PG_BS(z) (5120 + (z) * 15360) // Bs [192][40] half x2
#define PG_CS  35840                  // coords (512B)

__device__ __forceinline__ void gemm_part(char* smem, int gb,
                                          const float* F0, const float* F1,
                                          const float* F2, const float* F3) {
    __half* As_h = (__half*)(smem + SM_ASH);
    const uint32_t u_base = smem_u32(smem);
    const uint32_t u_bsh = u_base + SM_BSH;
    const uint32_t u_ash = u_base + SM_ASH;
    const uint32_t u_fs0 = u_base + SM_FS0;

    const int tid = threadIdx.x;
    const int lane = tid & 31, wid = tid >> 5;
    const int warp_m = wid & 1, warp_n = wid >> 1;   // 2m x 2n, warp tile 32px x 96d

    const int b = gb / TPB64;
    const int r = gb % TPB64;
    int level, tin;
    if (r < 256)      { level = 0; tin = r; }
    else if (r < 320) { level = 1; tin = r - 256; }
    else if (r < 336) { level = 2; tin = r - 320; }
    else              { level = 3; tin = r - 336; }
    const int HW = c_HW[level];
    const float* F = (level == 0) ? F0 : (level == 1) ? F1 : (level == 2) ? F2 : F3;
    F += (size_t)b * DM * HW + tin * 64;
    const __half* Wh = &g_Wbf[level][0][0];

    float acc[2][12][4];
#pragma unroll
    for (int mi = 0; mi < 2; mi++)
#pragma unroll
        for (int n = 0; n < 12; n++)
#pragma unroll
            for (int e = 0; e < 4; e++) acc[mi][n][e] = 0.0f;

    const int arow = lane & 15;
    const int acol8 = (lane >> 4) << 3;
    const int brow = (lane & 7) + ((lane >> 4) << 3);
    const int bcol8 = ((lane >> 3) & 1) << 3;
    const int px_cv = tid >> 1;
    const int q2 = tid & 1;

    const int fc = tid >> 4, fp4 = (tid & 15) << 2;
#define ISSUE_F(c0, buf) do { \
        uint32_t fdst = u_fs0 + (buf) * FS_SZ + fp4 * 4; \
        const float* fsrc = F + (size_t)((c0) + fc) * HW + fp4; \
        _Pragma("unroll") \
        for (int rr = 0; rr < 8; rr++) \
            CP_ASYNC16(fdst + (fc + rr * 8) * 272, fsrc + (size_t)(rr * 8) * HW); \
    } while (0)
#define ISSUE_B(c0) do { \
        _Pragma("unroll") \
        for (int ii = tid; ii < 1536; ii += 128) { \
            int d = ii >> 3, u = ii & 7; \
            uint32_t off = (uint32_t)(d * 144 + u * 16); \
            CP_ASYNC16(u_bsh + off, Wh + d * DM + (c0) + u * 8); \
        } \
    } while (0)

    ISSUE_F(0, 0);
    ISSUE_B(0);
    CP_COMMIT();

    for (int cz = 0; cz < 3; cz++) {
        const int c0 = cz * 64;
        const int buf = cz & 1;
        CP_WAIT0();
        __syncthreads();
        if (cz < 2) { ISSUE_F(c0 + 64, buf ^ 1); CP_COMMIT(); }

        // convert Fs[buf] -> As fp16 (transpose c<->px); each thread 32 halves
        const float* Fsb = (const float*)(smem + SM_FS0 + buf * FS_SZ);
#pragma unroll
        for (int g = 0; g < 4; g++) {
            union { unsigned short s[8]; uint4 v; } uh;
#pragma unroll
            for (int e = 0; e < 8; e++) {
                int c = q2 * 32 + g * 8 + e;
                __half h = __float2half_rn(Fsb[c * 68 + px_cv]);
                uh.s[e] = *(unsigned short*)&h;
            }
            *(uint4*)(As_h + px_cv * 72 + q2 * 32 + g * 8) = uh.v;
        }
        __syncthreads();

#pragma unroll
        for (int ks = 0; ks < 4; ks++) {
            const int k0 = ks * 16;
            uint32_t ah[2][4];
#pragma unroll
            for (int mi = 0; mi < 2; mi++) {
                uint32_t off = (uint32_t)((warp_m * 32 + mi * 16 + arow) * 72 + k0 + acol8) * 2;
                ldmx4(ah[mi], u_ash + off);
            }
            uint32_t bh[6][4];
#pragma unroll
            for (int nj = 0; nj < 6; nj++) {
                uint32_t off = (uint32_t)((warp_n * 96 + nj * 16 + brow) * 72 + k0 + bcol8) * 2;
                ldmx4(bh[nj], u_bsh + off);
            }
#pragma unroll
            for (int mi = 0; mi < 2; mi++)
#pragma unroll
                for (int n = 0; n < 12; n++)
                    mma_f16(acc[mi][n], ah[mi], bh[n >> 1][(n & 1) * 2],
                            bh[n >> 1][(n & 1) * 2 + 1]);
        }
        __syncthreads();
        if (cz < 2) { ISSUE_B(c0 + 64); CP_COMMIT(); }
    }

    // epilogue: fp16 writes
    const size_t rowbase = (size_t)b * PIX_PB + c_LOFF[level] + tin * 64 + warp_m * 32;
    const int dbase = warp_n * 96 + (lane & 3) * 2;
    const int rsub = lane >> 2;
#pragma unroll
    for (int mi = 0; mi < 2; mi++) {
        size_t r0 = (rowbase + mi * 16 + rsub) * DM;
        size_t r1 = (rowbase + mi * 16 + rsub + 8) * DM;
#pragma unroll
        for (int n = 0; n < 12; n++) {
            int d = dbase + n * 8;
            *(__half2*)(g_P + r0 + d) = __floats2half2_rn(acc[mi][n][0], acc[mi][n][1]);
            *(__half2*)(g_P + r1 + d) = __floats2half2_rn(acc[mi][n][2], acc[mi][n][3]);
        }
    }
}

__device__ __forceinline__ void pe_part(char* smem, int pb,
                                        const float* __restrict__ coords,
                                        const float* __restrict__ Wpos_b,
                                        float* __restrict__ out_pos,
                                        float* __restrict__ out_cg) {
    __half* As0 = (__half*)(smem + PG_AS0);
    float* cs = (float*)(smem + PG_CS);
    const uint32_t u_base = smem_u32(smem);

    const int p0 = pb * 64;
    const int tid = threadIdx.x;
    const int lane = tid & 31, wid = tid >> 5;
    const int warp_m = wid & 1, warp_n = wid >> 1;

    cs[tid] = coords[(size_t)p0 * 2 + tid];
#pragma unroll
    for (int i = tid; i < 768; i += 128) {
        int d = i >> 2, u = i & 3;
#pragma unroll
        for (int z = 0; z < 2; z++)
            *(uint4*)(smem + PG_BS(z) + (d * 40 + u * 8) * 2) =
                *(const uint4*)(&g_Wbfpe[z][d][0] + u * 8);
    }
    __syncthreads();

#pragma unroll
    for (int i = tid; i < 1024; i += 128) {
        int p = i >> 4, k = i & 15;
        int s = k >> 3, fq = k & 7;
        float c = cs[p * 2 + s];
        float arg = c * (1.0f / 512.0f) * (float)(1 << fq) * 6.283185307179586f;
        float sv, cv;
        sincosf(arg, &sv, &cv);
        int js = s * 16 + fq, jc = js + 8;
        As0[p * 40 + js] = __float2half_rn(sv);
        As0[p * 40 + jc] = __float2half_rn(cv);
    }
    if (tid < 64) {
        int gp = p0 + tid;
        out_cg[(size_t)gp * 2 + 0] = 2.0f * cs[tid * 2 + 0] / 511.0f - 1.0f;
        out_cg[(size_t)gp * 2 + 1] = 2.0f * cs[tid * 2 + 1] / 511.0f - 1.0f;
    }

    // ---- gather metadata: 2 threads per point, 2 levels each ----
    {
        int p = tid >> 1, h = tid & 1;
        int gp = p0 + p;
        int bb = gp >> 12;                       // / KPTS
        float cx = cs[p * 2 + 0];
        float cy = cs[p * 2 + 1];
#pragma unroll
        for (int li = 0; li < 2; li++) {
            int l = h * 2 + li;
            int W = c_Wd[l];
            float ix = cx * (float)(W - 1) * (1.0f / 511.0f);
            float iy = cy * (float)(W - 1) * (1.0f / 511.0f);
            float fx0 = floorf(ix), fy0 = floorf(iy);
            float wx = ix - fx0, wy = iy - fy0;
            int x0 = min(max((int)fx0, 0), W - 1);
            int x1 = min(max((int)fx0 + 1, 0), W - 1);
            int y0 = min(max((int)fy0, 0), W - 1);
            int y1 = min(max((int)fy0 + 1, 0), W - 1);
            int rowb = bb * PIX_PB + c_LOFF[l];
            int4 offs;
            offs.x = (rowb + y0 * W + x0) * (DM * 2);
            offs.y = (rowb + y0 * W + x1) * (DM * 2);
            offs.z = (rowb + y1 * W + x0) * (DM * 2);
            offs.w = (rowb + y1 * W + x1) * (DM * 2);
            union { __half2 h2[4]; uint4 v; } wp;
            wp.h2[0] = __float2half2_rn((1.0f - wx) * (1.0f - wy));
            wp.h2[1] = __float2half2_rn(wx * (1.0f - wy));
            wp.h2[2] = __float2half2_rn((1.0f - wx) * wy);
            wp.h2[3] = __float2half2_rn(wx * wy);
            uint4* mp = g_meta + (size_t)gp * 8 + l * 2;
            mp[0] = *(uint4*)&offs;
            mp[1] = wp.v;
        }
    }
    __syncthreads();

    const int arow = lane & 15;
    const int acol8 = (lane >> 4) << 3;
    const int brow = (lane & 7) + ((lane >> 4) << 3);
    const int bcol8 = ((lane >> 3) & 1) << 3;

    uint32_t ah[2][2][4];   // [ks][mi]
#pragma unroll
    for (int ks = 0; ks < 2; ks++)
#pragma unroll
        for (int mi = 0; mi < 2; mi++) {
            uint32_t off = (uint32_t)((warp_m * 32 + mi * 16 + arow) * 40 + ks * 16 + acol8) * 2;
            ldmx4(ah[ks][mi], u_base + PG_AS0 + off);
        }

    const int dbase = warp_n * 96 + (lane & 3) * 2;
    const int rsub = lane >> 2;

#pragma unroll
    for (int z = 0; z < 2; z++) {
        float acc[2][12][4];
#pragma unroll
        for (int mi = 0; mi < 2; mi++)
#pragma unroll
            for (int n = 0; n < 12; n++)
#pragma unroll
                for (int e = 0; e < 4; e++) acc[mi][n][e] = 0.0f;

#pragma unroll
        for (int ks = 0; ks < 2; ks++) {
            uint32_t bh[6][4];
#pragma unroll
            for (int nj = 0; nj < 6; nj++) {
                uint32_t off = (uint32_t)((warp_n * 96 + nj * 16 + brow) * 40 + ks * 16 + bcol8) * 2;
                ldmx4(bh[nj], u_base + PG_BS(z) + off);
            }
#pragma unroll
            for (int mi = 0; mi < 2; mi++)
#pragma unroll
                for (int n = 0; n < 12; n++)
                    mma_f16(acc[mi][n], ah[ks][mi], bh[n >> 1][(n & 1) * 2],
                            bh[n >> 1][(n & 1) * 2 + 1]);
        }

        const size_t rowbase = (size_t)p0 + warp_m * 32;
#pragma unroll
        for (int mi = 0; mi < 2; mi++) {
            size_t r0 = (rowbase + mi * 16 + rsub) * DM;
            size_t r1 = (rowbase + mi * 16 + rsub + 8) * DM;
#pragma unroll
            for (int n = 0; n < 12; n++) {
                int d = dbase + n * 8;
                if (z == 0) {
                    *(__half2*)(g_peW + r0 + d) = __floats2half2_rn(acc[mi][n][0], acc[mi][n][1]);
                    *(__half2*)(g_peW + r1 + d) = __floats2half2_rn(acc[mi][n][2], acc[mi][n][3]);
                } else {
                    float b0 = __ldg(Wpos_b + d), b1 = __ldg(Wpos_b + d + 1);
                    *(float2*)(out_pos + r0 + d) = make_float2(acc[mi][n][0] + b0,
                                                               acc[mi][n][1] + b1);
                    *(float2*)(out_pos + r1 + d) = make_float2(acc[mi][n][2] + b0,
                                                               acc[mi][n][3] + b1);
                }
            }
        }
    }
}

__global__ void __launch_bounds__(128, 3) k_main(const float* __restrict__ F0,
                                                 const float* __restrict__ F1,
                                                 const float* __restrict__ F2,
                                                 const float* __restrict__ F3,
                                                 const float* __restrict__ coords,
                                                 const float* __restrict__ Wpos_b,
                                                 float* __restrict__ out_pos,
                                                 float* __restrict__ out_cg) {
    extern __shared__ char smem[];
    if (blockIdx.x < NGEMM_BLK)
        gemm_part(smem, blockIdx.x, F0, F1, F2, F3);
    else
        pe_part(smem, blockIdx.x - NGEMM_BLK, coords, Wpos_b, out_pos, out_cg);
}

// ---------------------------------------------------------------------------
// Kernel 3: gather + bilinear + LayerNorm (1 warp = 1 point)
// Uses precomputed g_meta (corner offsets + fp16 weights) — no coord math.
// ---------------------------------------------------------------------------
__global__ void __launch_bounds__(256) k_gather(const float* __restrict__ seed_b,
                                                const float* __restrict__ lng,
                                                const float* __restrict__ lnb,
                                                float* __restrict__ out_seed) {
    const int wid = threadIdx.x >> 5;
    const int lane = threadIdx.x & 31;
    const int gp = blockIdx.x * 8 + wid;
    const int l4 = lane * 4;
    const int l2 = 128 + lane * 2;

    const __half* peW = g_peW + (size_t)gp * DM;
    float4 a4;
    float2 a2;
    {
        float4 s4 = __ldg((const float4*)(seed_b + l4));
        uint2 praw = __ldg((const uint2*)(peW + l4));
        float2 p01 = __half22float2(*(const __half2*)&praw.x);
        float2 p23 = __half22float2(*(const __half2*)&praw.y);
        a4 = make_float4(s4.x + p01.x, s4.y + p01.y, s4.z + p23.x, s4.w + p23.y);
        float2 s2 = __ldg((const float2*)(seed_b + l2));
        uint32_t praw2 = __ldg((const uint32_t*)(peW + l2));
        float2 p45 = __half22float2(*(const __half2*)&praw2);
        a2 = make_float2(s2.x + p45.x, s2.y + p45.y);
    }

    const uint4* mp = g_meta + (size_t)gp * 8;
    const char* base = (const char*)g_P;

#pragma unroll
    for (int l = 0; l < 4; l++) {
        uint4 ov = __ldg(mp + l * 2);
        uint4 wv = __ldg(mp + l * 2 + 1);
        const __half* cp[4] = {(const __half*)(base + ov.x),
                               (const __half*)(base + ov.y),
                               (const __half*)(base + ov.z),
                               (const __half*)(base + ov.w)};
        const __half2 hw[4] = {*(const __half2*)&wv.x, *(const __half2*)&wv.y,
                               *(const __half2*)&wv.z, *(const __half2*)&wv.w};
        __half2 s01 = __float2half2_rn(0.0f);
        __half2 s23 = __float2half2_rn(0.0f);
        __half2 s45 = __float2half2_rn(0.0f);
#pragma unroll
        for (int c = 0; c < 4; c++) {
            uint2 raw = __ldg((const uint2*)(cp[c] + l4));
            uint32_t raw2 = __ldg((const uint32_t*)(cp[c] + l2));
            s01 = __hfma2(*(const __half2*)&raw.x, hw[c], s01);
            s23 = __hfma2(*(const __half2*)&raw.y, hw[c], s23);
            s45 = __hfma2(*(const __half2*)&raw2, hw[c], s45);
        }
        float2 f01 = __half22float2(s01);
        float2 f23 = __half22float2(s23);
        float2 f45 = __half22float2(s45);
        a4.x += f01.x; a4.y += f01.y;
        a4.z += f23.x; a4.w += f23.y;
        a2.x += f45.x; a2.y += f45.y;
    }

    float s = a4.x + a4.y + a4.z + a4.w + a2.x + a2.y;
    float s2 = a4.x * a4.x + a4.y * a4.y + a4.z * a4.z + a4.w * a4.w
             + a2.x * a2.x + a2.y * a2.y;
#pragma unroll
    for (int o = 16; o > 0; o >>= 1) {
        s  += __shfl_xor_sync(0xFFFFFFFFu, s, o);
        s2 += __shfl_xor_sync(0xFFFFFFFFu, s2, o);
    }
    const float mu = s * (1.0f / 192.0f);
    const float var = s2 * (1.0f / 192.0f) - mu * mu;
    const float inv = rsqrtf(var + 1e-5f);

    float* dst = out_seed + (size_t)gp * DM;
    {
        float4 g4 = __ldg((const float4*)(lng + l4));
        float4 b4 = __ldg((const float4*)(lnb + l4));
        float4 o4 = make_float4((a4.x - mu) * inv * g4.x + b4.x,
                                (a4.y - mu) * inv * g4.y + b4.y,
                                (a4.z - mu) * inv * g4.z + b4.z,
                                (a4.w - mu) * inv * g4.w + b4.w);
        *(float4*)(dst + l4) = o4;
        float2 g2 = __ldg((const float2*)(lng + l2));
        float2 b2 = __ldg((const float2*)(lnb + l2));
        *(float2*)(dst + l2) = make_float2((a2.x - mu) * inv * g2.x + b2.x,
                                           (a2.y - mu) * inv * g2.y + b2.y);
    }
}

// ---------------------------------------------------------------------------
// launch
// ---------------------------------------------------------------------------
extern "C" void kernel_launch(void* const* d_in, const int* in_sizes, int n_in,
                              void* d_out, int out_size) {
    const float* coords  = (const float*)d_in[0];
    const float* L1      = (const float*)d_in[1];
    const float* L2      = (const float*)d_in[2];
    const float* L3      = (const float*)d_in[3];
    const float* L4      = (const float*)d_in[4];
    const float* Wseed_w = (const float*)d_in[5];
    const float* Wseed_b = (const float*)d_in[6];
    const float* ln_g    = (const float*)d_in[7];
    const float* ln_b    = (const float*)d_in[8];
    const float* Wpos_w  = (const float*)d_in[9];
    const float* Wpos_b  = (const float*)d_in[10];

    float* out      = (float*)d_out;
    float* out_seed = out;
    float* out_pos  = out + (size_t)NPTS * DM;
    float* out_cg   = out + (size_t)2 * NPTS * DM;

    cudaFuncSetAttribute(k_main, cudaFuncAttributeMaxDynamicSharedMemorySize, SMEM_MAIN);

    k_prep<<<(PREP_N + 255) / 256, 256>>>(Wseed_w, Wpos_w);
    k_main<<<NGEMM_BLK + NPE_BLK, 128, SMEM_MAIN>>>(L1, L2, L3, L4,
                                                    coords, Wpos_b, out_pos, out_cg);
    k_gather<<<NPTS / 8, 256>>>(Wseed_b, ln_g, ln_b, out_seed);
}

// round 13
// speedup vs baseline: 1.0671x; 1.0671x over previous
#include <cuda_runtime.h>
#include <cuda_fp16.h>
#include <cstdint>

// ---------------------------------------------------------------------------
// Problem constants
// ---------------------------------------------------------------------------
#define BATCH     8
#define KPTS      4096
#define NPTS      (BATCH * KPTS)      // 32768
#define DM        192
#define DIN       800
#define PEW       32
#define PIX_PB    21760               // 16384+4096+1024+256
#define TPB64     340                 // 64-px tiles per batch
#define NPE_BLK   (NPTS / 64)         // 512
#define NGEMM_BLK (BATCH * TPB64)     // 2720

__device__ __constant__ int c_HW[4]    = {16384, 4096, 1024, 256};
__device__ __constant__ int c_Wd[4]    = {128, 64, 32, 16};
__device__ __constant__ int c_LOFF[4]  = {0, 16384, 20480, 21504};

// ---------------------------------------------------------------------------
// Static device scratch
// ---------------------------------------------------------------------------
__device__ __half g_P[(size_t)BATCH * PIX_PB * DM];   // projected maps [pix][d] fp16
__device__ __half g_peW[(size_t)NPTS * DM];           // PE @ Wseed_pe^T  (fp16)
__device__ __half g_Wbf[4][DM][DM];                   // [level][d][c] fp16
__device__ __half g_Wbfpe[2][DM][PEW];                // [z][d][j]

// ---------------------------------------------------------------------------
// PTX helpers (generic sm_80+ — safe on compute_103 target)
// ---------------------------------------------------------------------------
__device__ __forceinline__ uint32_t smem_u32(const void* p) {
    uint32_t a;
    asm("{ .reg .u64 t; cvta.to.shared.u64 t, %1; cvt.u32.u64 %0, t; }" : "=r"(a) : "l"(p));
    return a;
}
__device__ __forceinline__ void ldmx4(uint32_t r[4], uint32_t addr) {
    asm volatile("ldmatrix.sync.aligned.m8n8.x4.shared.b16 {%0,%1,%2,%3}, [%4];"
                 : "=r"(r[0]), "=r"(r[1]), "=r"(r[2]), "=r"(r[3]) : "r"(addr));
}
__device__ __forceinline__ void mma_f16(float c[4], const uint32_t a[4],
                                        uint32_t b0, uint32_t b1) {
    asm volatile("mma.sync.aligned.m16n8k16.row.col.f32.f16.f16.f32 "
                 "{%0,%1,%2,%3}, {%4,%5,%6,%7}, {%8,%9}, {%0,%1,%2,%3};"
                 : "+f"(c[0]), "+f"(c[1]), "+f"(c[2]), "+f"(c[3])
                 : "r"(a[0]), "r"(a[1]), "r"(a[2]), "r"(a[3]), "r"(b0), "r"(b1));
}
#define CP_ASYNC16(dst, src) \
    asm volatile("cp.async.cg.shared.global [%0], [%1], 16;" \
                 :: "r"(dst), "l"(src) : "memory")
#define CP_COMMIT()  asm volatile("cp.async.commit_group;" ::: "memory")
#define CP_WAIT0()   asm volatile("cp.async.wait_group 0;" ::: "memory")

// ---------------------------------------------------------------------------
// Kernel 1: weight prep — fp16 weights (float4-vectorized)
// ---------------------------------------------------------------------------
#define PREP_N ((4 * DM * DM + 2 * DM * PEW) / 4)
__global__ void __launch_bounds__(256) k_prep(const float* __restrict__ Wseed_w,
                                              const float* __restrict__ Wpos_w) {
    int idx = blockIdx.x * 256 + threadIdx.x;
    if (idx < DM * DM) {
        int l = (idx * 4) / (DM * DM);
        int rem = (idx * 4) % (DM * DM);
        int d = rem / DM, c = rem % DM;
        float4 w = *(const float4*)(Wseed_w + (size_t)d * DIN + l * DM + c);
        __half* dst = &g_Wbf[l][d][c];
        dst[0] = __float2half_rn(w.x); dst[1] = __float2half_rn(w.y);
        dst[2] = __float2half_rn(w.z); dst[3] = __float2half_rn(w.w);
    } else if (idx < PREP_N) {
        int i2 = (idx - DM * DM) * 4;
        int z = i2 / (DM * PEW);
        int rem = i2 % (DM * PEW);
        int d = rem / PEW, j = rem % PEW;
        const float* src = z ? (Wpos_w + (size_t)d * PEW + j)
                             : (Wseed_w + (size_t)d * DIN + 768 + j);
        float4 w = *(const float4*)src;
        __half* dst = &g_Wbfpe[z][d][j];
        dst[0] = __float2half_rn(w.x); dst[1] = __float2half_rn(w.y);
        dst[2] = __float2half_rn(w.z); dst[3] = __float2half_rn(w.w);
    }
}

// ---------------------------------------------------------------------------
// Fused main kernel (128 threads/block, 3 CTAs/SM):
//   blocks [0, NGEMM_BLK):          projection GEMM (64px x 192d per block)
//   blocks [NGEMM_BLK, +NPE_BLK):   PE + dual GEMM + center_grid
// gemm smem: Bs x2 swizzled [192][64] (24576 each), As [64][72] (9216),
//            Fs single [64][68] fp32 (17408) -> total 75776
// ---------------------------------------------------------------------------
#define SM_BS0 0
#define BS_SZ  24576
#define SM_ASH 49152
#define SM_FS  58368
#define SMEM_MAIN 75776
// pegemm-part smem layout (within same allocation)
#define PG_AS0 0                      // As [64][40] half = 5120
#define PG_BS(z) (5120 + (z) * 15360) // Bs [192][40] half x2
#define PG_CS  35840                  // coords (512B)

__device__ __forceinline__ void gemm_part(char* smem, int gb,
                                          const float* F0, const float* F1,
                                          const float* F2, const float* F3) {
    __half* As_h = (__half*)(smem + SM_ASH);
    const uint32_t u_base = smem_u32(smem);
    const uint32_t u_bs0 = u_base + SM_BS0;
    const uint32_t u_ash = u_base + SM_ASH;
    const uint32_t u_fs = u_base + SM_FS;

    const int tid = threadIdx.x;
    const int lane = tid & 31, wid = tid >> 5;
    const int warp_m = wid & 1, warp_n = wid >> 1;   // 2m x 2n, warp tile 32px x 96d

    const int b = gb / TPB64;
    const int r = gb % TPB64;
    int level, tin;
    if (r < 256)      { level = 0; tin = r; }
    else if (r < 320) { level = 1; tin = r - 256; }
    else if (r < 336) { level = 2; tin = r - 320; }
    else              { level = 3; tin = r - 336; }
    const int HW = c_HW[level];
    const float* F = (level == 0) ? F0 : (level == 1) ? F1 : (level == 2) ? F2 : F3;
    F += (size_t)b * DM * HW + tin * 64;
    const __half* Wh = &g_Wbf[level][0][0];

    float acc[2][12][4];
#pragma unroll
    for (int mi = 0; mi < 2; mi++)
#pragma unroll
        for (int n = 0; n < 12; n++)
#pragma unroll
            for (int e = 0; e < 4; e++) acc[mi][n][e] = 0.0f;

    const int arow = lane & 15;
    const int acol8 = (lane >> 4) << 3;
    const int brow = (lane & 7) + ((lane >> 4) << 3);
    const int bcol8 = ((lane >> 3) & 1) << 3;
    const int px_cv = tid >> 1;
    const int q2 = tid & 1;

    const int fc = tid >> 4, fp4 = (tid & 15) << 2;
#define ISSUE_F(c0) do { \
        uint32_t fdst = u_fs + fp4 * 4; \
        const float* fsrc = F + (size_t)((c0) + fc) * HW + fp4; \
        _Pragma("unroll") \
        for (int rr = 0; rr < 8; rr++) \
            CP_ASYNC16(fdst + (fc + rr * 8) * 272, fsrc + (size_t)(rr * 8) * HW); \
    } while (0)
    // swizzled B: [192 d][64 c] halves, 128B rows, 16B chunks XOR'd by (d&7)<<4
#define ISSUE_B(c0, bb) do { \
        _Pragma("unroll") \
        for (int ii = tid; ii < 1536; ii += 128) { \
            int d = ii >> 3, u = ii & 7; \
            uint32_t off = (uint32_t)(d * 128 + ((u * 16) ^ ((d & 7) << 4))); \
            CP_ASYNC16(u_bs0 + (bb) * BS_SZ + off, Wh + d * DM + (c0) + u * 8); \
        } \
    } while (0)

    ISSUE_B(0, 0);
    ISSUE_F(0);
    CP_COMMIT();

    for (int cz = 0; cz < 3; cz++) {
        const int c0 = cz * 64;
        CP_WAIT0();
        __syncthreads();

        // prefetch NEXT B immediately (into the other buffer) — full-iteration window
        if (cz < 2) { ISSUE_B(c0 + 64, (cz + 1) & 1); CP_COMMIT(); }

        // convert Fs -> As fp16 (transpose c<->px); packed half2 converts
        const float* Fsb = (const float*)(smem + SM_FS);
#pragma unroll
        for (int g = 0; g < 4; g++) {
            union { __half2 h2[4]; uint4 v; } uh;
#pragma unroll
            for (int e2 = 0; e2 < 4; e2++) {
                int c = q2 * 32 + g * 8 + e2 * 2;
                uh.h2[e2] = __floats2half2_rn(Fsb[c * 68 + px_cv],
                                              Fsb[(c + 1) * 68 + px_cv]);
            }
            *(uint4*)(As_h + px_cv * 72 + q2 * 32 + g * 8) = uh.v;
        }
        __syncthreads();
        // Fs now free: prefetch next F — covered by the MMA phase
        if (cz < 2) { ISSUE_F(c0 + 64); CP_COMMIT(); }

        const uint32_t u_bs = u_bs0 + (cz & 1) * BS_SZ;
#pragma unroll
        for (int ks = 0; ks < 4; ks++) {
            const int k0 = ks * 16;
            uint32_t ah[2][4];
#pragma unroll
            for (int mi = 0; mi < 2; mi++) {
                uint32_t off = (uint32_t)((warp_m * 32 + mi * 16 + arow) * 72 + k0 + acol8) * 2;
                ldmx4(ah[mi], u_ash + off);
            }
            uint32_t bh[6][4];
#pragma unroll
            for (int nj = 0; nj < 6; nj++) {
                int browg = warp_n * 96 + nj * 16 + brow;
                uint32_t off = (uint32_t)(browg * 128 +
                               (((k0 + bcol8) * 2) ^ ((browg & 7) << 4)));
                ldmx4(bh[nj], u_bs + off);
            }
#pragma unroll
            for (int mi = 0; mi < 2; mi++)
#pragma unroll
                for (int n = 0; n < 12; n++)
                    mma_f16(acc[mi][n], ah[mi], bh[n >> 1][(n & 1) * 2],
                            bh[n >> 1][(n & 1) * 2 + 1]);
        }
        __syncthreads();
    }

    // epilogue: fp16 writes
    const size_t rowbase = (size_t)b * PIX_PB + c_LOFF[level] + tin * 64 + warp_m * 32;
    const int dbase = warp_n * 96 + (lane & 3) * 2;
    const int rsub = lane >> 2;
#pragma unroll
    for (int mi = 0; mi < 2; mi++) {
        size_t r0 = (rowbase + mi * 16 + rsub) * DM;
        size_t r1 = (rowbase + mi * 16 + rsub + 8) * DM;
#pragma unroll
        for (int n = 0; n < 12; n++) {
            int d = dbase + n * 8;
            *(__half2*)(g_P + r0 + d) = __floats2half2_rn(acc[mi][n][0], acc[mi][n][1]);
            *(__half2*)(g_P + r1 + d) = __floats2half2_rn(acc[mi][n][2], acc[mi][n][3]);
        }
    }
}

__device__ __forceinline__ void pe_part(char* smem, int pb,
                                        const float* __restrict__ coords,
                                        const float* __restrict__ Wpos_b,
                                        float* __restrict__ out_pos,
                                        float* __restrict__ out_cg) {
    __half* As0 = (__half*)(smem + PG_AS0);
    float* cs = (float*)(smem + PG_CS);
    const uint32_t u_base = smem_u32(smem);

    const int p0 = pb * 64;
    const int tid = threadIdx.x;
    const int lane = tid & 31, wid = tid >> 5;
    const int warp_m = wid & 1, warp_n = wid >> 1;

    cs[tid] = coords[(size_t)p0 * 2 + tid];
#pragma unroll
    for (int i = tid; i < 768; i += 128) {
        int d = i >> 2, u = i & 3;
#pragma unroll
        for (int z = 0; z < 2; z++)
            *(uint4*)(smem + PG_BS(z) + (d * 40 + u * 8) * 2) =
                *(const uint4*)(&g_Wbfpe[z][d][0] + u * 8);
    }
    __syncthreads();

#pragma unroll
    for (int i = tid; i < 1024; i += 128) {
        int p = i >> 4, k = i & 15;
        int s = k >> 3, fq = k & 7;
        float c = cs[p * 2 + s];
        float arg = c * (1.0f / 512.0f) * (float)(1 << fq) * 6.283185307179586f;
        float sv, cv;
        sincosf(arg, &sv, &cv);
        int js = s * 16 + fq, jc = js + 8;
        As0[p * 40 + js] = __float2half_rn(sv);
        As0[p * 40 + jc] = __float2half_rn(cv);
    }
    if (tid < 64) {
        int gp = p0 + tid;
        out_cg[(size_t)gp * 2 + 0] = 2.0f * cs[tid * 2 + 0] / 511.0f - 1.0f;
        out_cg[(size_t)gp * 2 + 1] = 2.0f * cs[tid * 2 + 1] / 511.0f - 1.0f;
    }
    __syncthreads();

    const int arow = lane & 15;
    const int acol8 = (lane >> 4) << 3;
    const int brow = (lane & 7) + ((lane >> 4) << 3);
    const int bcol8 = ((lane >> 3) & 1) << 3;

    uint32_t ah[2][2][4];   // [ks][mi]
#pragma unroll
    for (int ks = 0; ks < 2; ks++)
#pragma unroll
        for (int mi = 0; mi < 2; mi++) {
            uint32_t off = (uint32_t)((warp_m * 32 + mi * 16 + arow) * 40 + ks * 16 + acol8) * 2;
            ldmx4(ah[ks][mi], u_base + PG_AS0 + off);
        }

    const int dbase = warp_n * 96 + (lane & 3) * 2;
    const int rsub = lane >> 2;

#pragma unroll
    for (int z = 0; z < 2; z++) {
        float acc[2][12][4];
#pragma unroll
        for (int mi = 0; mi < 2; mi++)
#pragma unroll
            for (int n = 0; n < 12; n++)
#pragma unroll
                for (int e = 0; e < 4; e++) acc[mi][n][e] = 0.0f;

#pragma unroll
        for (int ks = 0; ks < 2; ks++) {
            uint32_t bh[6][4];
#pragma unroll
            for (int nj = 0; nj < 6; nj++) {
                uint32_t off = (uint32_t)((warp_n * 96 + nj * 16 + brow) * 40 + ks * 16 + bcol8) * 2;
                ldmx4(bh[nj], u_base + PG_BS(z) + off);
            }
#pragma unroll
            for (int mi = 0; mi < 2; mi++)
#pragma unroll
                for (int n = 0; n < 12; n++)
                    mma_f16(acc[mi][n], ah[ks][mi], bh[n >> 1][(n & 1) * 2],
                            bh[n >> 1][(n & 1) * 2 + 1]);
        }

        const size_t rowbase = (size_t)p0 + warp_m * 32;
#pragma unroll
        for (int mi = 0; mi < 2; mi++) {
            size_t r0 = (rowbase + mi * 16 + rsub) * DM;
            size_t r1 = (rowbase + mi * 16 + rsub + 8) * DM;
#pragma unroll
            for (int n = 0; n < 12; n++) {
                int d = dbase + n * 8;
                if (z == 0) {
                    *(__half2*)(g_peW + r0 + d) = __floats2half2_rn(acc[mi][n][0], acc[mi][n][1]);
                    *(__half2*)(g_peW + r1 + d) = __floats2half2_rn(acc[mi][n][2], acc[mi][n][3]);
                } else {
                    float b0 = __ldg(Wpos_b + d), b1 = __ldg(Wpos_b + d + 1);
                    *(float2*)(out_pos + r0 + d) = make_float2(acc[mi][n][0] + b0,
                                                               acc[mi][n][1] + b1);
                    *(float2*)(out_pos + r1 + d) = make_float2(acc[mi][n][2] + b0,
                                                               acc[mi][n][3] + b1);
                }
            }
        }
    }
}

__global__ void __launch_bounds__(128, 3) k_main(const float* __restrict__ F0,
                                                 const float* __restrict__ F1,
                                                 const float* __restrict__ F2,
                                                 const float* __restrict__ F3,
                                                 const float* __restrict__ coords,
                                                 const float* __restrict__ Wpos_b,
                                                 float* __restrict__ out_pos,
                                                 float* __restrict__ out_cg) {
    extern __shared__ char smem[];
    if (blockIdx.x < NGEMM_BLK)
        gemm_part(smem, blockIdx.x, F0, F1, F2, F3);
    else
        pe_part(smem, blockIdx.x - NGEMM_BLK, coords, Wpos_b, out_pos, out_cg);
}

// ---------------------------------------------------------------------------
// Kernel 3: gather + bilinear + LayerNorm (1 warp = 1 point) — R11 version
// ---------------------------------------------------------------------------
__global__ void __launch_bounds__(256) k_gather(const float* __restrict__ coords,
                                                const float* __restrict__ seed_b,
                                                const float* __restrict__ lng,
                                                const float* __restrict__ lnb,
                                                float* __restrict__ out_seed) {
    const int b = blockIdx.y;
    const int wid = threadIdx.x >> 5;
    const int lane = threadIdx.x & 31;
    const int k = blockIdx.x * 8 + wid;
    const int gp = b * KPTS + k;
    const int l4 = lane * 4;
    const int l2 = 128 + lane * 2;

    const float cx = coords[(size_t)gp * 2 + 0];
    const float cy = coords[(size_t)gp * 2 + 1];
    const float gx = 2.0f * cx / 511.0f - 1.0f;
    const float gy = 2.0f * cy / 511.0f - 1.0f;

    const __half* peW = g_peW + (size_t)gp * DM;
    float4 a4;
    float2 a2;
    {
        float4 s4 = __ldg((const float4*)(seed_b + l4));
        uint2 praw = __ldg((const uint2*)(peW + l4));
        float2 p01 = __half22float2(*(const __half2*)&praw.x);
        float2 p23 = __half22float2(*(const __half2*)&praw.y);
        a4 = make_float4(s4.x + p01.x, s4.y + p01.y, s4.z + p23.x, s4.w + p23.y);
        float2 s2 = __ldg((const float2*)(seed_b + l2));
        uint32_t praw2 = __ldg((const uint32_t*)(peW + l2));
        float2 p45 = __half22float2(*(const __half2*)&praw2);
        a2 = make_float2(s2.x + p45.x, s2.y + p45.y);
    }

#pragma unroll
    for (int l = 0; l < 4; l++) {
        const int W = c_Wd[l];
        const float ix = (gx + 1.0f) * 0.5f * (float)(W - 1);
        const float iy = (gy + 1.0f) * 0.5f * (float)(W - 1);
        const float fx0 = floorf(ix);
        const float fy0 = floorf(iy);
        const float wx = ix - fx0;
        const float wy = iy - fy0;
        int x0 = min(max((int)fx0, 0), W - 1);
        int x1 = min(max((int)fx0 + 1, 0), W - 1);
        int y0 = min(max((int)fy0, 0), W - 1);
        int y1 = min(max((int)fy0 + 1, 0), W - 1);
        const size_t base = ((size_t)b * PIX_PB + c_LOFF[l]) * DM;
        const __half* cp[4] = {g_P + base + (size_t)(y0 * W + x0) * DM,
                               g_P + base + (size_t)(y0 * W + x1) * DM,
                               g_P + base + (size_t)(y1 * W + x0) * DM,
                               g_P + base + (size_t)(y1 * W + x1) * DM};
        const __half2 hw[4] = {
            __float2half2_rn((1.0f - wx) * (1.0f - wy)),
            __float2half2_rn(wx * (1.0f - wy)),
            __float2half2_rn((1.0f - wx) * wy),
            __float2half2_rn(wx * wy)};
        __half2 s01 = __float2half2_rn(0.0f);
        __half2 s23 = __float2half2_rn(0.0f);
        __half2 s45 = __float2half2_rn(0.0f);
#pragma unroll
        for (int c = 0; c < 4; c++) {
            uint2 raw = __ldg((const uint2*)(cp[c] + l4));
            uint32_t raw2 = __ldg((const uint32_t*)(cp[c] + l2));
            s01 = __hfma2(*(const __half2*)&raw.x, hw[c], s01);
            s23 = __hfma2(*(const __half2*)&raw.y, hw[c], s23);
            s45 = __hfma2(*(const __half2*)&raw2, hw[c], s45);
        }
        float2 f01 = __half22float2(s01);
        float2 f23 = __half22float2(s23);
        float2 f45 = __half22float2(s45);
        a4.x += f01.x; a4.y += f01.y;
        a4.z += f23.x; a4.w += f23.y;
        a2.x += f45.x; a2.y += f45.y;
    }

    float s = a4.x + a4.y + a4.z + a4.w + a2.x + a2.y;
    float s2 = a4.x * a4.x + a4.y * a4.y + a4.z * a4.z + a4.w * a4.w
             + a2.x * a2.x + a2.y * a2.y;
#pragma unroll
    for (int o = 16; o > 0; o >>= 1) {
        s  += __shfl_xor_sync(0xFFFFFFFFu, s, o);
        s2 += __shfl_xor_sync(0xFFFFFFFFu, s2, o);
    }
    const float mu = s * (1.0f / 192.0f);
    const float var = s2 * (1.0f / 192.0f) - mu * mu;
    const float inv = rsqrtf(var + 1e-5f);

    float* dst = out_seed + (size_t)gp * DM;
    {
        float4 g4 = __ldg((const float4*)(lng + l4));
        float4 b4 = __ldg((const float4*)(lnb + l4));
        float4 o4 = make_float4((a4.x - mu) * inv * g4.x + b4.x,
                                (a4.y - mu) * inv * g4.y + b4.y,
                                (a4.z - mu) * inv * g4.z + b4.z,
                                (a4.w - mu) * inv * g4.w + b4.w);
        *(float4*)(dst + l4) = o4;
        float2 g2 = __ldg((const float2*)(lng + l2));
        float2 b2 = __ldg((const float2*)(lnb + l2));
        *(float2*)(dst + l2) = make_float2((a2.x - mu) * inv * g2.x + b2.x,
                                           (a2.y - mu) * inv * g2.y + b2.y);
    }
}

// ---------------------------------------------------------------------------
// launch
// ---------------------------------------------------------------------------
extern "C" void kernel_launch(void* const* d_in, const int* in_sizes, int n_in,
                              void* d_out, int out_size) {
    const float* coords  = (const float*)d_in[0];
    const float* L1      = (const float*)d_in[1];
    const float* L2      = (const float*)d_in[2];
    const float* L3      = (const float*)d_in[3];
    const float* L4      = (const float*)d_in[4];
    const float* Wseed_w = (const float*)d_in[5];
    const float* Wseed_b = (const float*)d_in[6];
    const float* ln_g    = (const float*)d_in[7];
    const float* ln_b    = (const float*)d_in[8];
    const float* Wpos_w  = (const float*)d_in[9];
    const float* Wpos_b  = (const float*)d_in[10];

    float* out      = (float*)d_out;
    float* out_seed = out;
    float* out_pos  = out + (size_t)NPTS * DM;
    float* out_cg   = out + (size_t)2 * NPTS * DM;

    cudaFuncSetAttribute(k_main, cudaFuncAttributeMaxDynamicSharedMemorySize, SMEM_MAIN);

    k_prep<<<(PREP_N + 255) / 256, 256>>>(Wseed_w, Wpos_w);
    k_main<<<NGEMM_BLK + NPE_BLK, 128, SMEM_MAIN>>>(L1, L2, L3, L4,
                                                    coords, Wpos_b, out_pos, out_cg);
    k_gather<<<dim3(KPTS / 8, BATCH), 256>>>(coords, Wseed_b, ln_g, ln_b, out_seed);
}